// round 1
// baseline (speedup 1.0000x reference)
#include <cuda_runtime.h>

#define B_ 32
#define C_ 256
#define H_ 96
#define W_ 96
#define HW_ (H_*W_)            // 9216
#define NPIX (B_*HW_)          // 294912
#define NPIX4 (NPIX/4)         // 73728
#define NELEM (B_*C_*HW_)      // 75497472
#define NELEM4 (NELEM/4)       // 18874368

// Scratch (allocation-free rule: __device__ globals)
__device__ float  g_catmap[2*NPIX];   // [b][ci][hw], ci=0 max, ci=1 avg
__device__ float  g_conv[NPIX];
__device__ float  g_w[NPIX];
__device__ double g_sum, g_sumsq;
__device__ float  g_stats[3];         // mu, scale(=invstd*gamma), beta

__global__ void init_k() { g_sum = 0.0; g_sumsq = 0.0; }

// ---------------- Pass 1: channel max + mean ----------------
__global__ void reduce_k(const float* __restrict__ x) {
    int t = blockIdx.x * 256 + threadIdx.x;
    if (t >= NPIX4) return;
    int pix = t * 4;
    int b  = pix / HW_;
    int hw = pix - b * HW_;
    const float4* xp = reinterpret_cast<const float4*>(x + (size_t)b * C_ * HW_ + hw);
    const int cs = HW_ / 4;

    float4 v = xp[0];
    float mx0 = v.x, mx1 = v.y, mx2 = v.z, mx3 = v.w;
    float s0 = v.x, s1 = v.y, s2 = v.z, s3 = v.w;
    #pragma unroll 8
    for (int c = 1; c < C_; c++) {
        float4 u = xp[(size_t)c * cs];
        mx0 = fmaxf(mx0, u.x); mx1 = fmaxf(mx1, u.y);
        mx2 = fmaxf(mx2, u.z); mx3 = fmaxf(mx3, u.w);
        s0 += u.x; s1 += u.y; s2 += u.z; s3 += u.w;
    }
    const float inv = 1.0f / (float)C_;
    float* cm = g_catmap + (size_t)b * 2 * HW_;
    *reinterpret_cast<float4*>(cm + hw)       = make_float4(mx0, mx1, mx2, mx3);
    *reinterpret_cast<float4*>(cm + HW_ + hw) = make_float4(s0*inv, s1*inv, s2*inv, s3*inv);
}

// ---------------- Offset conv + deformable sample + def conv + BN stats ----------------
__global__ void deform_k(const float* __restrict__ w_off, const float* __restrict__ b_off,
                         const float* __restrict__ w_def, const float* __restrict__ b_def) {
    int p = blockIdx.x * 256 + threadIdx.x;
    float convv = 0.f;
    if (p < NPIX) {
        int b  = p / HW_;
        int hw = p - b * HW_;
        int y  = hw / W_;
        int xx = hw - y * W_;
        const float* cm = g_catmap + (size_t)b * 2 * HW_;

        // 3x3 neighborhood, both channels, zero-padded
        float nb[2][9];
        #pragma unroll
        for (int iy = 0; iy < 3; iy++) {
            int yy = y + iy - 1;
            #pragma unroll
            for (int ix = 0; ix < 3; ix++) {
                int xc = xx + ix - 1;
                bool ok = (yy >= 0 && yy < H_ && xc >= 0 && xc < W_);
                int idx = ok ? (yy * W_ + xc) : 0;
                nb[0][iy*3 + ix] = ok ? cm[idx]        : 0.f;
                nb[1][iy*3 + ix] = ok ? cm[HW_ + idx]  : 0.f;
            }
        }

        float acc = b_def[0];
        #pragma unroll
        for (int k = 0; k < 9; k++) {
            // offset conv channels o=2k (dy), o=2k+1 (dx); w_off[o][ci][3][3]
            float dy = b_off[2*k], dx = b_off[2*k + 1];
            #pragma unroll
            for (int ci = 0; ci < 2; ci++) {
                #pragma unroll
                for (int t9 = 0; t9 < 9; t9++) {
                    dy = fmaf(w_off[(2*k)   * 18 + ci*9 + t9], nb[ci][t9], dy);
                    dx = fmaf(w_off[(2*k+1) * 18 + ci*9 + t9], nb[ci][t9], dx);
                }
            }
            float py = (float)y  + (float)(k / 3) - 1.f + dy;
            float px = (float)xx + (float)(k % 3) - 1.f + dx;
            float fy0 = floorf(py), fx0 = floorf(px);
            int   y0 = (int)fy0,  x0 = (int)fx0;
            float ly = py - fy0,  lx = px - fx0;
            int   y1 = y0 + 1,    x1 = x0 + 1;
            float w00 = (1.f - ly) * (1.f - lx), w01 = (1.f - ly) * lx;
            float w10 = ly * (1.f - lx),         w11 = ly * lx;
            bool iy0 = (y0 >= 0 && y0 < H_), iy1 = (y1 >= 0 && y1 < H_);
            bool ix0 = (x0 >= 0 && x0 < W_), ix1 = (x1 >= 0 && x1 < W_);
            int cy0 = min(max(y0, 0), H_-1), cy1 = min(max(y1, 0), H_-1);
            int cx0 = min(max(x0, 0), W_-1), cx1 = min(max(x1, 0), W_-1);
            float m00 = (iy0 && ix0) ? w00 : 0.f, m01 = (iy0 && ix1) ? w01 : 0.f;
            float m10 = (iy1 && ix0) ? w10 : 0.f, m11 = (iy1 && ix1) ? w11 : 0.f;
            int i00 = cy0*W_ + cx0, i01 = cy0*W_ + cx1;
            int i10 = cy1*W_ + cx0, i11 = cy1*W_ + cx1;
            #pragma unroll
            for (int ci = 0; ci < 2; ci++) {
                const float* ch = cm + ci * HW_;
                float s = ch[i00]*m00 + ch[i01]*m01 + ch[i10]*m10 + ch[i11]*m11;
                acc = fmaf(s, w_def[ci*9 + k], acc);
            }
        }
        convv = acc;
        g_conv[p] = convv;
    }

    // block reduce for BN stats
    __shared__ float ssum[256];
    __shared__ float ssq[256];
    int tid = threadIdx.x;
    ssum[tid] = convv;
    ssq[tid]  = convv * convv;
    __syncthreads();
    for (int s = 128; s > 0; s >>= 1) {
        if (tid < s) { ssum[tid] += ssum[tid + s]; ssq[tid] += ssq[tid + s]; }
        __syncthreads();
    }
    if (tid == 0) {
        atomicAdd(&g_sum,   (double)ssum[0]);
        atomicAdd(&g_sumsq, (double)ssq[0]);
    }
}

__global__ void finalize_k(const float* __restrict__ gamma, const float* __restrict__ beta) {
    double mu  = g_sum / (double)NPIX;
    double var = g_sumsq / (double)NPIX - mu * mu;
    float invstd = (float)(1.0 / sqrt(var + 1e-5));
    g_stats[0] = (float)mu;
    g_stats[1] = invstd * gamma[0];
    g_stats[2] = beta[0];
}

__global__ void wcomp_k() {
    int t = blockIdx.x * 256 + threadIdx.x;
    if (t >= NPIX4) return;
    float mu = g_stats[0], sc = g_stats[1], be = g_stats[2];
    float4 c = reinterpret_cast<const float4*>(g_conv)[t];
    float4 r;
    r.x = 1.f / (1.f + __expf(-((c.x - mu) * sc + be)));
    r.y = 1.f / (1.f + __expf(-((c.y - mu) * sc + be)));
    r.z = 1.f / (1.f + __expf(-((c.z - mu) * sc + be)));
    r.w = 1.f / (1.f + __expf(-((c.w - mu) * sc + be)));
    reinterpret_cast<float4*>(g_w)[t] = r;
}

// ---------------- Pass 2: out = x * w[pixel] ----------------
__global__ void mul_k(const float* __restrict__ x, float* __restrict__ out) {
    int t = blockIdx.x * 256 + threadIdx.x;   // float4 index, < NELEM4
    int b   = t / (C_ * HW_ / 4);
    int hw4 = t % (HW_ / 4);
    float4 wv = reinterpret_cast<const float4*>(g_w)[b * (HW_ / 4) + hw4];
    float4 xv = reinterpret_cast<const float4*>(x)[t];
    float4 o;
    o.x = xv.x * wv.x; o.y = xv.y * wv.y; o.z = xv.z * wv.z; o.w = xv.w * wv.w;
    reinterpret_cast<float4*>(out)[t] = o;
}

extern "C" void kernel_launch(void* const* d_in, const int* in_sizes, int n_in,
                              void* d_out, int out_size) {
    const float* x     = (const float*)d_in[0];
    const float* w_off = (const float*)d_in[1];
    const float* b_off = (const float*)d_in[2];
    const float* w_def = (const float*)d_in[3];
    const float* b_def = (const float*)d_in[4];
    const float* gamma = (const float*)d_in[5];
    const float* beta  = (const float*)d_in[6];
    float* out = (float*)d_out;

    init_k<<<1, 1>>>();
    reduce_k<<<NPIX4 / 256, 256>>>(x);
    deform_k<<<NPIX / 256, 256>>>(w_off, b_off, w_def, b_def);
    finalize_k<<<1, 1>>>(gamma, beta);
    wcomp_k<<<NPIX4 / 256, 256>>>();
    mul_k<<<NELEM4 / 256, 256>>>(x, out);
}

// round 3
// speedup vs baseline: 1.0332x; 1.0332x over previous
#include <cuda_runtime.h>

#define B_ 32
#define C_ 256
#define H_ 96
#define W_ 96
#define HW_ (H_*W_)            // 9216
#define NPIX (B_*HW_)          // 294912
#define NPIX4 (NPIX/4)         // 73728
#define NELEM (B_*C_*HW_)      // 75497472
#define NELEM4 (NELEM/4)       // 18874368
#define NELEM8 (NELEM/8)       // 9437184

// Scratch (allocation-free rule: __device__ globals)
__device__ float  g_catmap[2*NPIX];   // [b][ci][hw], ci=0 max, ci=1 avg
__device__ float  g_conv[NPIX];
__device__ float  g_w[NPIX];
__device__ double g_sum, g_sumsq;

// ---------------- Pass 1: channel max + mean (also zeroes BN accumulators) ----
// (Race-free: the accumulators are only atomically updated by deform_k, which
//  launches after this kernel completes in stream order.)
__global__ __launch_bounds__(256) void reduce_k(const float* __restrict__ x) {
    if (blockIdx.x == 0 && threadIdx.x == 0) { g_sum = 0.0; g_sumsq = 0.0; }
    int t = blockIdx.x * 256 + threadIdx.x;
    if (t >= NPIX4) return;
    int pix = t * 4;
    int b  = pix / HW_;
    int hw = pix - b * HW_;
    const float4* xp = reinterpret_cast<const float4*>(x + (size_t)b * C_ * HW_ + hw);
    const int cs = HW_ / 4;

    float4 v = xp[0];
    float mx0 = v.x, mx1 = v.y, mx2 = v.z, mx3 = v.w;
    float s0 = v.x, s1 = v.y, s2 = v.z, s3 = v.w;
    #pragma unroll 16
    for (int c = 1; c < C_; c++) {
        float4 u = __ldg(&xp[(size_t)c * cs]);
        mx0 = fmaxf(mx0, u.x); mx1 = fmaxf(mx1, u.y);
        mx2 = fmaxf(mx2, u.z); mx3 = fmaxf(mx3, u.w);
        s0 += u.x; s1 += u.y; s2 += u.z; s3 += u.w;
    }
    const float inv = 1.0f / (float)C_;
    float* cm = g_catmap + (size_t)b * 2 * HW_;
    *reinterpret_cast<float4*>(cm + hw)       = make_float4(mx0, mx1, mx2, mx3);
    *reinterpret_cast<float4*>(cm + HW_ + hw) = make_float4(s0*inv, s1*inv, s2*inv, s3*inv);
}

// ---------------- Offset conv + deformable sample + def conv + BN stats ----------------
__global__ __launch_bounds__(256) void deform_k(const float* __restrict__ w_off, const float* __restrict__ b_off,
                         const float* __restrict__ w_def, const float* __restrict__ b_def) {
    int p = blockIdx.x * 256 + threadIdx.x;
    float convv = 0.f;
    {
        int b  = p / HW_;
        int hw = p - b * HW_;
        int y  = hw / W_;
        int xx = hw - y * W_;
        const float* cm = g_catmap + (size_t)b * 2 * HW_;

        // 3x3 neighborhood, both channels, zero-padded
        float nb[2][9];
        #pragma unroll
        for (int iy = 0; iy < 3; iy++) {
            int yy = y + iy - 1;
            #pragma unroll
            for (int ix = 0; ix < 3; ix++) {
                int xc = xx + ix - 1;
                bool ok = (yy >= 0 && yy < H_ && xc >= 0 && xc < W_);
                int idx = ok ? (yy * W_ + xc) : 0;
                nb[0][iy*3 + ix] = ok ? cm[idx]        : 0.f;
                nb[1][iy*3 + ix] = ok ? cm[HW_ + idx]  : 0.f;
            }
        }

        float acc = b_def[0];
        #pragma unroll
        for (int k = 0; k < 9; k++) {
            // offset conv channels o=2k (dy), o=2k+1 (dx); w_off[o][ci][3][3]
            float dy = b_off[2*k], dx = b_off[2*k + 1];
            #pragma unroll
            for (int ci = 0; ci < 2; ci++) {
                #pragma unroll
                for (int t9 = 0; t9 < 9; t9++) {
                    dy = fmaf(w_off[(2*k)   * 18 + ci*9 + t9], nb[ci][t9], dy);
                    dx = fmaf(w_off[(2*k+1) * 18 + ci*9 + t9], nb[ci][t9], dx);
                }
            }
            float py = (float)y  + (float)(k / 3) - 1.f + dy;
            float px = (float)xx + (float)(k % 3) - 1.f + dx;
            float fy0 = floorf(py), fx0 = floorf(px);
            int   y0 = (int)fy0,  x0 = (int)fx0;
            float ly = py - fy0,  lx = px - fx0;
            int   y1 = y0 + 1,    x1 = x0 + 1;
            float w00 = (1.f - ly) * (1.f - lx), w01 = (1.f - ly) * lx;
            float w10 = ly * (1.f - lx),         w11 = ly * lx;
            bool iy0 = (y0 >= 0 && y0 < H_), iy1 = (y1 >= 0 && y1 < H_);
            bool ix0 = (x0 >= 0 && x0 < W_), ix1 = (x1 >= 0 && x1 < W_);
            int cy0 = min(max(y0, 0), H_-1), cy1 = min(max(y1, 0), H_-1);
            int cx0 = min(max(x0, 0), W_-1), cx1 = min(max(x1, 0), W_-1);
            float m00 = (iy0 && ix0) ? w00 : 0.f, m01 = (iy0 && ix1) ? w01 : 0.f;
            float m10 = (iy1 && ix0) ? w10 : 0.f, m11 = (iy1 && ix1) ? w11 : 0.f;
            int i00 = cy0*W_ + cx0, i01 = cy0*W_ + cx1;
            int i10 = cy1*W_ + cx0, i11 = cy1*W_ + cx1;
            #pragma unroll
            for (int ci = 0; ci < 2; ci++) {
                const float* ch = cm + ci * HW_;
                float s = ch[i00]*m00 + ch[i01]*m01 + ch[i10]*m10 + ch[i11]*m11;
                acc = fmaf(s, w_def[ci*9 + k], acc);
            }
        }
        convv = acc;
        g_conv[p] = convv;
    }

    // block reduce for BN stats
    __shared__ float ssum[256];
    __shared__ float ssq[256];
    int tid = threadIdx.x;
    ssum[tid] = convv;
    ssq[tid]  = convv * convv;
    __syncthreads();
    for (int s = 128; s > 32; s >>= 1) {
        if (tid < s) { ssum[tid] += ssum[tid + s]; ssq[tid] += ssq[tid + s]; }
        __syncthreads();
    }
    if (tid < 32) {
        float a = ssum[tid] + ssum[tid + 32];
        float q = ssq[tid]  + ssq[tid + 32];
        #pragma unroll
        for (int o = 16; o > 0; o >>= 1) {
            a += __shfl_down_sync(0xffffffff, a, o);
            q += __shfl_down_sync(0xffffffff, q, o);
        }
        if (tid == 0) {
            atomicAdd(&g_sum,   (double)a);
            atomicAdd(&g_sumsq, (double)q);
        }
    }
}

// ---------------- BN finalize + sigmoid gate (stats recomputed per thread) ---
__global__ __launch_bounds__(256) void wcomp_k(const float* __restrict__ gamma, const float* __restrict__ beta) {
    int t = blockIdx.x * 256 + threadIdx.x;
    if (t >= NPIX4) return;
    double mud  = g_sum / (double)NPIX;
    double var  = g_sumsq / (double)NPIX - mud * mud;
    float invstd = (float)(1.0 / sqrt(var + 1e-5));
    float mu = (float)mud;
    float sc = invstd * gamma[0];
    float be = beta[0];
    float4 c = reinterpret_cast<const float4*>(g_conv)[t];
    float4 r;
    r.x = 1.f / (1.f + __expf(-((c.x - mu) * sc + be)));
    r.y = 1.f / (1.f + __expf(-((c.y - mu) * sc + be)));
    r.z = 1.f / (1.f + __expf(-((c.z - mu) * sc + be)));
    r.w = 1.f / (1.f + __expf(-((c.w - mu) * sc + be)));
    reinterpret_cast<float4*>(g_w)[t] = r;
}

// ---------------- Pass 2: out = x * w[pixel], 2 float4 per thread ------------
__global__ __launch_bounds__(256) void mul_k(const float* __restrict__ x, float* __restrict__ out) {
    int t = blockIdx.x * 256 + threadIdx.x;   // each handles 2 float4s, NELEM8 threads
    const float4* xp = reinterpret_cast<const float4*>(x);
    const float4* wp = reinterpret_cast<const float4*>(g_w);
    float4*       op = reinterpret_cast<float4*>(out);
    #pragma unroll
    for (int j = 0; j < 2; j++) {
        int i = t + j * NELEM8;               // two independent streams, both coalesced
        int b   = i / (C_ * HW_ / 4);
        int hw4 = i % (HW_ / 4);
        float4 wv = wp[b * (HW_ / 4) + hw4];
        float4 xv = xp[i];
        float4 o;
        o.x = xv.x * wv.x; o.y = xv.y * wv.y; o.z = xv.z * wv.z; o.w = xv.w * wv.w;
        op[i] = o;
    }
}

extern "C" void kernel_launch(void* const* d_in, const int* in_sizes, int n_in,
                              void* d_out, int out_size) {
    const float* x     = (const float*)d_in[0];
    const float* w_off = (const float*)d_in[1];
    const float* b_off = (const float*)d_in[2];
    const float* w_def = (const float*)d_in[3];
    const float* b_def = (const float*)d_in[4];
    const float* gamma = (const float*)d_in[5];
    const float* beta  = (const float*)d_in[6];
    float* out = (float*)d_out;

    reduce_k<<<NPIX4 / 256, 256>>>(x);
    deform_k<<<NPIX / 256, 256>>>(w_off, b_off, w_def, b_def);
    wcomp_k<<<NPIX4 / 256, 256>>>(gamma, beta);
    mul_k<<<NELEM8 / 256, 256>>>(x, out);
}

// round 4
// speedup vs baseline: 1.0347x; 1.0015x over previous
#include <cuda_runtime.h>

#define B_ 32
#define C_ 256
#define H_ 96
#define W_ 96
#define HW_ (H_*W_)            // 9216
#define NPIX (B_*HW_)          // 294912
#define NPIX4 (NPIX/4)         // 73728
#define NELEM (B_*C_*HW_)      // 75497472
#define NELEM4 (NELEM/4)       // 18874368
#define NELEM8 (NELEM/8)       // 9437184

// Scratch (allocation-free rule: __device__ globals)
__device__ float  g_catmap[2*NPIX];   // [b][ci][hw], ci=0 max, ci=1 avg
__device__ float  g_conv[NPIX];
__device__ float  g_w[NPIX];
__device__ double g_sum, g_sumsq;

// ---------------- Pass 1: channel max + mean (also zeroes BN accumulators) ----
// (Race-free: the accumulators are only atomically updated by deform_k, which
//  launches after this kernel completes in stream order.)
__global__ __launch_bounds__(256) void reduce_k(const float* __restrict__ x) {
    if (blockIdx.x == 0 && threadIdx.x == 0) { g_sum = 0.0; g_sumsq = 0.0; }
    int t = blockIdx.x * 256 + threadIdx.x;
    if (t >= NPIX4) return;
    int pix = t * 4;
    int b  = pix / HW_;
    int hw = pix - b * HW_;
    const float4* xp = reinterpret_cast<const float4*>(x + (size_t)b * C_ * HW_ + hw);
    const int cs = HW_ / 4;

    float4 v = xp[0];
    float mx0 = v.x, mx1 = v.y, mx2 = v.z, mx3 = v.w;
    float s0 = v.x, s1 = v.y, s2 = v.z, s3 = v.w;
    #pragma unroll 16
    for (int c = 1; c < C_; c++) {
        float4 u = __ldg(&xp[(size_t)c * cs]);
        mx0 = fmaxf(mx0, u.x); mx1 = fmaxf(mx1, u.y);
        mx2 = fmaxf(mx2, u.z); mx3 = fmaxf(mx3, u.w);
        s0 += u.x; s1 += u.y; s2 += u.z; s3 += u.w;
    }
    const float inv = 1.0f / (float)C_;
    float* cm = g_catmap + (size_t)b * 2 * HW_;
    *reinterpret_cast<float4*>(cm + hw)       = make_float4(mx0, mx1, mx2, mx3);
    *reinterpret_cast<float4*>(cm + HW_ + hw) = make_float4(s0*inv, s1*inv, s2*inv, s3*inv);
}

// ---------------- Offset conv + deformable sample + def conv + BN stats ----------------
__global__ __launch_bounds__(256) void deform_k(const float* __restrict__ w_off, const float* __restrict__ b_off,
                         const float* __restrict__ w_def, const float* __restrict__ b_def) {
    int p = blockIdx.x * 256 + threadIdx.x;
    float convv = 0.f;
    {
        int b  = p / HW_;
        int hw = p - b * HW_;
        int y  = hw / W_;
        int xx = hw - y * W_;
        const float* cm = g_catmap + (size_t)b * 2 * HW_;

        // 3x3 neighborhood, both channels, zero-padded
        float nb[2][9];
        #pragma unroll
        for (int iy = 0; iy < 3; iy++) {
            int yy = y + iy - 1;
            #pragma unroll
            for (int ix = 0; ix < 3; ix++) {
                int xc = xx + ix - 1;
                bool ok = (yy >= 0 && yy < H_ && xc >= 0 && xc < W_);
                int idx = ok ? (yy * W_ + xc) : 0;
                nb[0][iy*3 + ix] = ok ? cm[idx]        : 0.f;
                nb[1][iy*3 + ix] = ok ? cm[HW_ + idx]  : 0.f;
            }
        }

        float acc = b_def[0];
        #pragma unroll
        for (int k = 0; k < 9; k++) {
            // offset conv channels o=2k (dy), o=2k+1 (dx); w_off[o][ci][3][3]
            float dy = b_off[2*k], dx = b_off[2*k + 1];
            #pragma unroll
            for (int ci = 0; ci < 2; ci++) {
                #pragma unroll
                for (int t9 = 0; t9 < 9; t9++) {
                    dy = fmaf(w_off[(2*k)   * 18 + ci*9 + t9], nb[ci][t9], dy);
                    dx = fmaf(w_off[(2*k+1) * 18 + ci*9 + t9], nb[ci][t9], dx);
                }
            }
            float py = (float)y  + (float)(k / 3) - 1.f + dy;
            float px = (float)xx + (float)(k % 3) - 1.f + dx;
            float fy0 = floorf(py), fx0 = floorf(px);
            int   y0 = (int)fy0,  x0 = (int)fx0;
            float ly = py - fy0,  lx = px - fx0;
            int   y1 = y0 + 1,    x1 = x0 + 1;
            float w00 = (1.f - ly) * (1.f - lx), w01 = (1.f - ly) * lx;
            float w10 = ly * (1.f - lx),         w11 = ly * lx;
            bool iy0 = (y0 >= 0 && y0 < H_), iy1 = (y1 >= 0 && y1 < H_);
            bool ix0 = (x0 >= 0 && x0 < W_), ix1 = (x1 >= 0 && x1 < W_);
            int cy0 = min(max(y0, 0), H_-1), cy1 = min(max(y1, 0), H_-1);
            int cx0 = min(max(x0, 0), W_-1), cx1 = min(max(x1, 0), W_-1);
            float m00 = (iy0 && ix0) ? w00 : 0.f, m01 = (iy0 && ix1) ? w01 : 0.f;
            float m10 = (iy1 && ix0) ? w10 : 0.f, m11 = (iy1 && ix1) ? w11 : 0.f;
            int i00 = cy0*W_ + cx0, i01 = cy0*W_ + cx1;
            int i10 = cy1*W_ + cx0, i11 = cy1*W_ + cx1;
            #pragma unroll
            for (int ci = 0; ci < 2; ci++) {
                const float* ch = cm + ci * HW_;
                float s = ch[i00]*m00 + ch[i01]*m01 + ch[i10]*m10 + ch[i11]*m11;
                acc = fmaf(s, w_def[ci*9 + k], acc);
            }
        }
        convv = acc;
        g_conv[p] = convv;
    }

    // block reduce for BN stats
    __shared__ float ssum[256];
    __shared__ float ssq[256];
    int tid = threadIdx.x;
    ssum[tid] = convv;
    ssq[tid]  = convv * convv;
    __syncthreads();
    for (int s = 128; s > 32; s >>= 1) {
        if (tid < s) { ssum[tid] += ssum[tid + s]; ssq[tid] += ssq[tid + s]; }
        __syncthreads();
    }
    if (tid < 32) {
        float a = ssum[tid] + ssum[tid + 32];
        float q = ssq[tid]  + ssq[tid + 32];
        #pragma unroll
        for (int o = 16; o > 0; o >>= 1) {
            a += __shfl_down_sync(0xffffffff, a, o);
            q += __shfl_down_sync(0xffffffff, q, o);
        }
        if (tid == 0) {
            atomicAdd(&g_sum,   (double)a);
            atomicAdd(&g_sumsq, (double)q);
        }
    }
}

// ---------------- BN finalize + sigmoid gate (stats recomputed per thread) ---
__global__ __launch_bounds__(256) void wcomp_k(const float* __restrict__ gamma, const float* __restrict__ beta) {
    int t = blockIdx.x * 256 + threadIdx.x;
    if (t >= NPIX4) return;
    double mud  = g_sum / (double)NPIX;
    double var  = g_sumsq / (double)NPIX - mud * mud;
    float invstd = (float)(1.0 / sqrt(var + 1e-5));
    float mu = (float)mud;
    float sc = invstd * gamma[0];
    float be = beta[0];
    float4 c = reinterpret_cast<const float4*>(g_conv)[t];
    float4 r;
    r.x = 1.f / (1.f + __expf(-((c.x - mu) * sc + be)));
    r.y = 1.f / (1.f + __expf(-((c.y - mu) * sc + be)));
    r.z = 1.f / (1.f + __expf(-((c.z - mu) * sc + be)));
    r.w = 1.f / (1.f + __expf(-((c.w - mu) * sc + be)));
    reinterpret_cast<float4*>(g_w)[t] = r;
}

// ---------------- Pass 2: out = x * w[pixel], 2 float4 per thread ------------
__global__ __launch_bounds__(256) void mul_k(const float* __restrict__ x, float* __restrict__ out) {
    int t = blockIdx.x * 256 + threadIdx.x;   // each handles 2 float4s, NELEM8 threads
    const float4* xp = reinterpret_cast<const float4*>(x);
    const float4* wp = reinterpret_cast<const float4*>(g_w);
    float4*       op = reinterpret_cast<float4*>(out);
    #pragma unroll
    for (int j = 0; j < 2; j++) {
        int i = t + j * NELEM8;               // two independent streams, both coalesced
        int b   = i / (C_ * HW_ / 4);
        int hw4 = i % (HW_ / 4);
        float4 wv = wp[b * (HW_ / 4) + hw4];
        float4 xv = xp[i];
        float4 o;
        o.x = xv.x * wv.x; o.y = xv.y * wv.y; o.z = xv.z * wv.z; o.w = xv.w * wv.w;
        op[i] = o;
    }
}

extern "C" void kernel_launch(void* const* d_in, const int* in_sizes, int n_in,
                              void* d_out, int out_size) {
    const float* x     = (const float*)d_in[0];
    const float* w_off = (const float*)d_in[1];
    const float* b_off = (const float*)d_in[2];
    const float* w_def = (const float*)d_in[3];
    const float* b_def = (const float*)d_in[4];
    const float* gamma = (const float*)d_in[5];
    const float* beta  = (const float*)d_in[6];
    float* out = (float*)d_out;

    reduce_k<<<NPIX4 / 256, 256>>>(x);
    deform_k<<<NPIX / 256, 256>>>(w_off, b_off, w_def, b_def);
    wcomp_k<<<NPIX4 / 256, 256>>>(gamma, beta);
    mul_k<<<NELEM8 / 256, 256>>>(x, out);
}